// round 3
// baseline (speedup 1.0000x reference)
#include <cuda_runtime.h>

#define NN 50000
#define EE 800000
#define FF 64
#define GG 128

// ---------------- device scratch (static allocation only; no cudaMalloc) ----
__device__ __align__(16) float g_deg[NN];
__device__ __align__(16) float g_dinv[NN];
__device__ __align__(16) float g_agg[NN * FF];   // aggregation buffer (reused both layers)
__device__ __align__(16) float g_h1[NN * FF];    // relu(agg1 @ W1 + b1)
__device__ float g_pool[GG];
__device__ float g_cnt[GG];
__device__ int   g_ei64;   // 1 if edge_index stored as int64, else int32
__device__ int   g_b64;    // 1 if batch stored as int64

// Read index i from an array that may be int32 or little-endian int64 (hi=0).
__device__ __forceinline__ int loadIdx(const int* p, long long i, int is64) {
    return is64 ? p[2 * i] : p[(int)i];
}

// ---------------- dtype detection --------------------------------------------
__global__ void k_detect(const int* ei, const int* batch) {
    if (threadIdx.x == 0 && blockIdx.x == 0) {
        // edge_index: if int64, odd words are high halves == 0 (values in [0,N)).
        int or_odd = 0;
        #pragma unroll
        for (int i = 0; i < 8; i++) or_odd |= ei[2 * i + 1];
        g_ei64 = (or_odd == 0) ? 1 : 0;
        // batch: sorted ascending, tail values ~G-1 (nonzero). Probe odd word
        // positions near the end of the first NN words (safe for either dtype).
        int or_tail = 0;
        #pragma unroll
        for (int i = 0; i < 8; i++) {
            int w = NN - 1 - 2 * i;         // odd indices (NN even -> NN-1 odd)
            or_tail |= batch[w];
        }
        g_b64 = (or_tail == 0) ? 1 : 0;
    }
}

// ---------------- init --------------------------------------------------------
__global__ void k_init() {
    int i = blockIdx.x * blockDim.x + threadIdx.x;
    if (i < NN) g_deg[i] = 1.0f;               // self-loop
    if (i < GG) { g_pool[i] = 0.0f; g_cnt[i] = 0.0f; }
}

__global__ void k_deg(const int* ei) {
    int e = blockIdx.x * blockDim.x + threadIdx.x;
    if (e >= EE) return;
    int is64 = g_ei64;
    int d = loadIdx(ei, (long long)EE + e, is64);
    atomicAdd(&g_deg[d], 1.0f);
}

__global__ void k_cnt(const int* batch) {
    int i = blockIdx.x * blockDim.x + threadIdx.x;
    if (i >= NN) return;
    int g = loadIdx(batch, i, g_b64);
    atomicAdd(&g_cnt[g], 1.0f);
}

__global__ void k_dinv() {
    int i = blockIdx.x * blockDim.x + threadIdx.x;
    if (i < NN) g_dinv[i] = rsqrtf(g_deg[i]);
}

// agg[i] = feat[i] * dinv[i]^2   (self-loop term)
// LAYER 0: feat = x (kernel arg). LAYER 1: feat = g_h1 (device symbol, resolved
// IN DEVICE CODE -- passing a __device__ array as a host-side kernel argument
// silently yields the host shadow address on ATS-coherent GB300).
template <int LAYER>
__global__ void k_self(const float* __restrict__ featArg) {
    const float* feat = (LAYER == 0) ? featArg : (const float*)g_h1;
    int idx = blockIdx.x * blockDim.x + threadIdx.x;  // over NN*16 float4 slots
    if (idx >= NN * (FF / 4)) return;
    int i = idx >> 4;
    float w = g_dinv[i];
    w = w * w;
    float4 v = reinterpret_cast<const float4*>(feat)[idx];
    float4 r = make_float4(v.x * w, v.y * w, v.z * w, v.w * w);
    reinterpret_cast<float4*>(g_agg)[idx] = r;
}

// scatter-add: agg[dst] += norm(e) * feat[src], 16 threads (float4 each) per edge
template <int LAYER>
__global__ void k_edge(const float* __restrict__ featArg, const int* __restrict__ ei) {
    const float* feat = (LAYER == 0) ? featArg : (const float*)g_h1;
    long long tid = (long long)blockIdx.x * blockDim.x + threadIdx.x;
    if (tid >= (long long)EE * 16) return;
    int e = (int)(tid >> 4);
    int t = (int)(tid & 15);
    int is64 = g_ei64;
    int s = loadIdx(ei, e, is64);
    int d = loadIdx(ei, (long long)EE + e, is64);
    float w = g_dinv[s] * g_dinv[d];
    float4 v = reinterpret_cast<const float4*>(feat)[s * 16 + t];
    float* dstp = g_agg + d * FF + t * 4;
    atomicAdd(dstp + 0, v.x * w);
    atomicAdd(dstp + 1, v.y * w);
    atomicAdd(dstp + 2, v.z * w);
    atomicAdd(dstp + 3, v.w * w);
}

// h1 = relu(agg @ W1 + b1),  W1: [64,64]
__global__ void k_gemm1(const float* __restrict__ W1, const float* __restrict__ b1) {
    __shared__ __align__(16) float Ws[FF * FF];
    __shared__ __align__(16) float bs[FF];
    int tid = threadIdx.x;
    for (int k = tid; k < FF * FF; k += blockDim.x) Ws[k] = W1[k];
    if (tid < FF) bs[tid] = b1[tid];
    __syncthreads();

    int i = blockIdx.x * blockDim.x + tid;
    if (i >= NN) return;

    float a[FF];
    #pragma unroll
    for (int k4 = 0; k4 < FF / 4; k4++) {
        float4 v = reinterpret_cast<const float4*>(g_agg)[i * (FF / 4) + k4];
        a[4 * k4 + 0] = v.x; a[4 * k4 + 1] = v.y; a[4 * k4 + 2] = v.z; a[4 * k4 + 3] = v.w;
    }
    const float4* Ws4 = reinterpret_cast<const float4*>(Ws);
    const float4* bs4 = reinterpret_cast<const float4*>(bs);
    #pragma unroll
    for (int j4 = 0; j4 < FF / 4; j4++) {
        float4 acc = bs4[j4];
        #pragma unroll 16
        for (int k = 0; k < FF; k++) {
            float4 w = Ws4[k * (FF / 4) + j4];
            acc.x = fmaf(a[k], w.x, acc.x);
            acc.y = fmaf(a[k], w.y, acc.y);
            acc.z = fmaf(a[k], w.z, acc.z);
            acc.w = fmaf(a[k], w.w, acc.w);
        }
        acc.x = fmaxf(acc.x, 0.0f); acc.y = fmaxf(acc.y, 0.0f);
        acc.z = fmaxf(acc.z, 0.0f); acc.w = fmaxf(acc.w, 0.0f);
        reinterpret_cast<float4*>(g_h1)[i * (FF / 4) + j4] = acc;
    }
}

// fused: per node s_i = relu(agg_i @ W2 + b2) . fcW ;  pool[batch[i]] += s_i
// W2: [64,128], fcW: [128]
__global__ void k_gemm2_fused(const float* __restrict__ W2, const float* __restrict__ b2,
                              const float* __restrict__ fcW, const int* __restrict__ batch) {
    __shared__ __align__(16) float Ws[FF * 2 * FF];   // 32 KB
    __shared__ __align__(16) float bs[2 * FF];
    __shared__ __align__(16) float fs[2 * FF];
    int tid = threadIdx.x;
    for (int k = tid; k < FF * 2 * FF; k += blockDim.x) Ws[k] = W2[k];
    for (int k = tid; k < 2 * FF; k += blockDim.x) { bs[k] = b2[k]; fs[k] = fcW[k]; }
    __syncthreads();

    int i = blockIdx.x * blockDim.x + tid;
    if (i >= NN) return;

    float a[FF];
    #pragma unroll
    for (int k4 = 0; k4 < FF / 4; k4++) {
        float4 v = reinterpret_cast<const float4*>(g_agg)[i * (FF / 4) + k4];
        a[4 * k4 + 0] = v.x; a[4 * k4 + 1] = v.y; a[4 * k4 + 2] = v.z; a[4 * k4 + 3] = v.w;
    }
    const float4* Ws4 = reinterpret_cast<const float4*>(Ws);
    const float4* bs4 = reinterpret_cast<const float4*>(bs);
    const float4* fs4 = reinterpret_cast<const float4*>(fs);
    float s = 0.0f;
    #pragma unroll 4
    for (int j4 = 0; j4 < (2 * FF) / 4; j4++) {
        float4 acc = bs4[j4];
        #pragma unroll 16
        for (int k = 0; k < FF; k++) {
            float4 w = Ws4[k * (2 * FF / 4) + j4];
            acc.x = fmaf(a[k], w.x, acc.x);
            acc.y = fmaf(a[k], w.y, acc.y);
            acc.z = fmaf(a[k], w.z, acc.z);
            acc.w = fmaf(a[k], w.w, acc.w);
        }
        acc.x = fmaxf(acc.x, 0.0f); acc.y = fmaxf(acc.y, 0.0f);
        acc.z = fmaxf(acc.z, 0.0f); acc.w = fmaxf(acc.w, 0.0f);
        float4 f = fs4[j4];
        s = fmaf(acc.x, f.x, s); s = fmaf(acc.y, f.y, s);
        s = fmaf(acc.z, f.z, s); s = fmaf(acc.w, f.w, s);
    }
    int g = loadIdx(batch, i, g_b64);
    atomicAdd(&g_pool[g], s);
}

__global__ void k_final(float* __restrict__ out, const float* __restrict__ fcb) {
    int g = threadIdx.x;
    if (g < GG) out[g] = g_pool[g] / fmaxf(g_cnt[g], 1.0f) + fcb[0];
}

// ---------------- launch ------------------------------------------------------
extern "C" void kernel_launch(void* const* d_in, const int* in_sizes, int n_in,
                              void* d_out, int out_size) {
    const float* x     = (const float*)d_in[0];
    const int*   ei    = (const int*)d_in[1];
    const int*   batch = (const int*)d_in[2];
    const float* W1    = (const float*)d_in[3];
    const float* b1    = (const float*)d_in[4];
    const float* W2    = (const float*)d_in[5];
    const float* b2    = (const float*)d_in[6];
    const float* fcW   = (const float*)d_in[7];
    const float* fcb   = (const float*)d_in[8];
    float* out = (float*)d_out;

    const int T = 256;
    k_detect<<<1, 32>>>(ei, batch);
    k_init<<<(NN + T - 1) / T, T>>>();
    k_deg<<<(EE + T - 1) / T, T>>>(ei);
    k_cnt<<<(NN + T - 1) / T, T>>>(batch);
    k_dinv<<<(NN + T - 1) / T, T>>>();

    // layer 1: agg = A_hat @ x ; h1 = relu(agg @ W1 + b1)
    k_self<0><<<(NN * (FF / 4) + T - 1) / T, T>>>(x);
    k_edge<0><<<(int)(((long long)EE * 16 + T - 1) / T), T>>>(x, ei);
    k_gemm1<<<(NN + T - 1) / T, T>>>(W1, b1);

    // layer 2: agg = A_hat @ h1 ; fused gemm+relu+fc+pool (h1 resolved in device code)
    k_self<1><<<(NN * (FF / 4) + T - 1) / T, T>>>(nullptr);
    k_edge<1><<<(int)(((long long)EE * 16 + T - 1) / T), T>>>(nullptr, ei);
    k_gemm2_fused<<<(NN + T - 1) / T, T>>>(W2, b2, fcW, batch);

    k_final<<<1, GG>>>(out, fcb);
}

// round 4
// speedup vs baseline: 1.7298x; 1.7298x over previous
#include <cuda_runtime.h>

#define NN 50000
#define EE 800000
#define FF 64
#define GG 128

// ---------------- device scratch (static allocation only) --------------------
__device__ __align__(16) float g_deg[NN];
__device__ __align__(16) float g_dinv[NN];
__device__ __align__(16) float g_agg[NN * FF];   // aggregation buffer (both layers)
__device__ __align__(16) float g_h1[NN * FF];    // relu(agg1 @ W1 + b1)
__device__ float g_pool[GG];
__device__ float g_cnt[GG];
__device__ int   g_ei64;   // 1 if edge_index stored as int64, else int32
__device__ int   g_b64;    // 1 if batch stored as int64

// Read index i from an array that may be int32 or little-endian int64 (hi=0).
__device__ __forceinline__ int loadIdx(const int* p, long long i, int is64) {
    return is64 ? p[2 * i] : p[(int)i];
}

// ---------------- prep: dtype detect + per-graph counts + pool zero ----------
// batch is sorted ascending, so counts come from binary searches (no atomics).
__global__ void k_prep(const int* ei, const int* batch) {
    __shared__ int s_b64;
    int t = threadIdx.x;
    if (t == 0) {
        // edge_index: if int64, odd words are high halves == 0 (values < 2^31).
        int or_odd = 0;
        #pragma unroll
        for (int i = 0; i < 8; i++) or_odd |= ei[2 * i + 1];
        g_ei64 = (or_odd == 0) ? 1 : 0;
        // batch: sorted, tail values ~G-1 (nonzero). Probe odd word positions
        // near the end of the first NN words (valid range for either dtype).
        int or_tail = 0;
        #pragma unroll
        for (int i = 0; i < 8; i++) or_tail |= batch[NN - 1 - 2 * i];
        s_b64 = (or_tail == 0) ? 1 : 0;
        g_b64 = s_b64;
    }
    __syncthreads();
    int is64 = s_b64;
    if (t < GG) {
        g_pool[t] = 0.0f;
        // lower_bound(t) and lower_bound(t+1) over sorted batch
        int lo0 = 0, hi0 = NN, lo1 = 0, hi1 = NN;
        while (lo0 < hi0) { int m = (lo0 + hi0) >> 1; if (loadIdx(batch, m, is64) < t)     lo0 = m + 1; else hi0 = m; }
        while (lo1 < hi1) { int m = (lo1 + hi1) >> 1; if (loadIdx(batch, m, is64) < t + 1) lo1 = m + 1; else hi1 = m; }
        g_cnt[t] = (float)(lo1 - lo0);
    }
}

__global__ void k_init_deg() {
    int i = blockIdx.x * blockDim.x + threadIdx.x;
    if (i < NN) g_deg[i] = 1.0f;               // self-loop
}

__global__ void k_deg(const int* ei) {
    int e = blockIdx.x * blockDim.x + threadIdx.x;
    if (e >= EE) return;
    int d = loadIdx(ei, (long long)EE + e, g_ei64);
    atomicAdd(&g_deg[d], 1.0f);
}

__global__ void k_dinv() {
    int i = blockIdx.x * blockDim.x + threadIdx.x;
    if (i < NN) g_dinv[i] = rsqrtf(g_deg[i]);
}

// agg[i] = feat[i] * dinv[i]^2   (self-loop term)
template <int LAYER>
__global__ void k_self(const float* __restrict__ featArg) {
    const float* feat = (LAYER == 0) ? featArg : (const float*)g_h1;
    int idx = blockIdx.x * blockDim.x + threadIdx.x;  // over NN*16 float4 slots
    if (idx >= NN * (FF / 4)) return;
    int i = idx >> 4;
    float w = g_dinv[i];
    w = w * w;
    float4 v = reinterpret_cast<const float4*>(feat)[idx];
    reinterpret_cast<float4*>(g_agg)[idx] = make_float4(v.x * w, v.y * w, v.z * w, v.w * w);
}

// scatter-add: agg[dst] += norm(e) * feat[src]
// 16 threads per edge, ONE float4 vector atomic (RED.128) per thread.
template <int LAYER>
__global__ void k_edge(const float* __restrict__ featArg, const int* __restrict__ ei) {
    const float* feat = (LAYER == 0) ? featArg : (const float*)g_h1;
    long long tid = (long long)blockIdx.x * blockDim.x + threadIdx.x;
    if (tid >= (long long)EE * 16) return;
    int e = (int)(tid >> 4);
    int t = (int)(tid & 15);
    int is64 = g_ei64;
    int s = loadIdx(ei, e, is64);
    int d = loadIdx(ei, (long long)EE + e, is64);
    float w = g_dinv[s] * g_dinv[d];
    float4 v = reinterpret_cast<const float4*>(feat)[s * 16 + t];
    float4 r = make_float4(v.x * w, v.y * w, v.z * w, v.w * w);
    atomicAdd(reinterpret_cast<float4*>(g_agg) + d * (FF / 4) + t, r);  // RED.128 (sm_90+)
}

// h1 = relu(agg @ W1 + b1),  W1: [64,64]
__global__ void k_gemm1(const float* __restrict__ W1, const float* __restrict__ b1) {
    __shared__ __align__(16) float Ws[FF * FF];
    __shared__ __align__(16) float bs[FF];
    int tid = threadIdx.x;
    for (int k = tid; k < FF * FF; k += blockDim.x) Ws[k] = W1[k];
    if (tid < FF) bs[tid] = b1[tid];
    __syncthreads();

    int i = blockIdx.x * blockDim.x + tid;
    if (i >= NN) return;

    float a[FF];
    #pragma unroll
    for (int k4 = 0; k4 < FF / 4; k4++) {
        float4 v = reinterpret_cast<const float4*>(g_agg)[i * (FF / 4) + k4];
        a[4 * k4 + 0] = v.x; a[4 * k4 + 1] = v.y; a[4 * k4 + 2] = v.z; a[4 * k4 + 3] = v.w;
    }
    const float4* Ws4 = reinterpret_cast<const float4*>(Ws);
    const float4* bs4 = reinterpret_cast<const float4*>(bs);
    #pragma unroll
    for (int j4 = 0; j4 < FF / 4; j4++) {
        float4 acc = bs4[j4];
        #pragma unroll 16
        for (int k = 0; k < FF; k++) {
            float4 w = Ws4[k * (FF / 4) + j4];
            acc.x = fmaf(a[k], w.x, acc.x);
            acc.y = fmaf(a[k], w.y, acc.y);
            acc.z = fmaf(a[k], w.z, acc.z);
            acc.w = fmaf(a[k], w.w, acc.w);
        }
        acc.x = fmaxf(acc.x, 0.0f); acc.y = fmaxf(acc.y, 0.0f);
        acc.z = fmaxf(acc.z, 0.0f); acc.w = fmaxf(acc.w, 0.0f);
        reinterpret_cast<float4*>(g_h1)[i * (FF / 4) + j4] = acc;
    }
}

// fused: per node s_i = relu(agg_i @ W2 + b2) . fcW ;  pool[batch[i]] += s_i
// batch is sorted -> segmented warp suffix-reduction, one atomic per segment head.
__global__ void k_gemm2_fused(const float* __restrict__ W2, const float* __restrict__ b2,
                              const float* __restrict__ fcW, const int* __restrict__ batch) {
    __shared__ __align__(16) float Ws[FF * 2 * FF];   // 32 KB
    __shared__ __align__(16) float bs[2 * FF];
    __shared__ __align__(16) float fs[2 * FF];
    int tid = threadIdx.x;
    for (int k = tid; k < FF * 2 * FF; k += blockDim.x) Ws[k] = W2[k];
    for (int k = tid; k < 2 * FF; k += blockDim.x) { bs[k] = b2[k]; fs[k] = fcW[k]; }
    __syncthreads();

    int i = blockIdx.x * blockDim.x + tid;
    float s = 0.0f;
    int g = -1;
    if (i < NN) {
        g = loadIdx(batch, i, g_b64);
        float a[FF];
        #pragma unroll
        for (int k4 = 0; k4 < FF / 4; k4++) {
            float4 v = reinterpret_cast<const float4*>(g_agg)[i * (FF / 4) + k4];
            a[4 * k4 + 0] = v.x; a[4 * k4 + 1] = v.y; a[4 * k4 + 2] = v.z; a[4 * k4 + 3] = v.w;
        }
        const float4* Ws4 = reinterpret_cast<const float4*>(Ws);
        const float4* bs4 = reinterpret_cast<const float4*>(bs);
        const float4* fs4 = reinterpret_cast<const float4*>(fs);
        #pragma unroll 4
        for (int j4 = 0; j4 < (2 * FF) / 4; j4++) {
            float4 acc = bs4[j4];
            #pragma unroll 16
            for (int k = 0; k < FF; k++) {
                float4 w = Ws4[k * (2 * FF / 4) + j4];
                acc.x = fmaf(a[k], w.x, acc.x);
                acc.y = fmaf(a[k], w.y, acc.y);
                acc.z = fmaf(a[k], w.z, acc.z);
                acc.w = fmaf(a[k], w.w, acc.w);
            }
            acc.x = fmaxf(acc.x, 0.0f); acc.y = fmaxf(acc.y, 0.0f);
            acc.z = fmaxf(acc.z, 0.0f); acc.w = fmaxf(acc.w, 0.0f);
            float4 f = fs4[j4];
            s = fmaf(acc.x, f.x, s); s = fmaf(acc.y, f.y, s);
            s = fmaf(acc.z, f.z, s); s = fmaf(acc.w, f.w, s);
        }
    }
    // segmented suffix-sum over the warp (keys g are non-decreasing: batch sorted)
    unsigned lane = threadIdx.x & 31u;
    #pragma unroll
    for (int off = 1; off < 32; off <<= 1) {
        float o = __shfl_down_sync(0xffffffffu, s, off);
        int   og = __shfl_down_sync(0xffffffffu, g, off);
        if (lane + off < 32 && og == g) s += o;
    }
    int gprev = __shfl_up_sync(0xffffffffu, g, 1);
    if (g >= 0 && (lane == 0 || gprev != g)) atomicAdd(&g_pool[g], s);
}

__global__ void k_final(float* __restrict__ out, const float* __restrict__ fcb) {
    int g = threadIdx.x;
    if (g < GG) out[g] = g_pool[g] / fmaxf(g_cnt[g], 1.0f) + fcb[0];
}

// ---------------- launch ------------------------------------------------------
extern "C" void kernel_launch(void* const* d_in, const int* in_sizes, int n_in,
                              void* d_out, int out_size) {
    const float* x     = (const float*)d_in[0];
    const int*   ei    = (const int*)d_in[1];
    const int*   batch = (const int*)d_in[2];
    const float* W1    = (const float*)d_in[3];
    const float* b1    = (const float*)d_in[4];
    const float* W2    = (const float*)d_in[5];
    const float* b2    = (const float*)d_in[6];
    const float* fcW   = (const float*)d_in[7];
    const float* fcb   = (const float*)d_in[8];
    float* out = (float*)d_out;

    const int T = 256;
    k_prep<<<1, 128>>>(ei, batch);
    k_init_deg<<<(NN + T - 1) / T, T>>>();
    k_deg<<<(EE + T - 1) / T, T>>>(ei);
    k_dinv<<<(NN + T - 1) / T, T>>>();

    // layer 1: agg = A_hat @ x ; h1 = relu(agg @ W1 + b1)
    k_self<0><<<(NN * (FF / 4) + T - 1) / T, T>>>(x);
    k_edge<0><<<(int)(((long long)EE * 16 + T - 1) / T), T>>>(x, ei);
    k_gemm1<<<(NN + T - 1) / T, T>>>(W1, b1);

    // layer 2: agg = A_hat @ h1 ; fused gemm+relu+fc+pool
    k_self<1><<<(NN * (FF / 4) + T - 1) / T, T>>>(nullptr);
    k_edge<1><<<(int)(((long long)EE * 16 + T - 1) / T), T>>>(nullptr, ei);
    k_gemm2_fused<<<(NN + T - 1) / T, T>>>(W2, b2, fcW, batch);

    k_final<<<1, GG>>>(out, fcb);
}